// round 5
// baseline (speedup 1.0000x reference)
#include <cuda_runtime.h>

// DynamicConv2d: B=64, C=8, H=W=256, OUT_C=8, K=3, pad=1.
// R4: R3 design with the weight-index bug fixed (duplicated-weight u64 stride
//     is *8, not *4). f32x2 packed over COLUMN pairs (2 cols x 2 och per
//     thread), odd-offset smem layout => kw=0/kw=2 taps are direct aligned
//     LDS.64, duplicated-weight pairs, __launch_bounds__(256,3).

typedef unsigned long long u64;

#define TY 8                    // output rows per tile
#define TX 128                  // output cols per tile
#define SIN_STRIDE 136          // row stride (floats); col cx stored at cx+3
#define SIN_ROWS (TY + 2)       // 10
#define SIN_PER_C (SIN_ROWS * SIN_STRIDE)     // 1360
#define SMEM_W 1152             // duplicated weights: 72*8*2
#define SMEM_FLOATS (SMEM_W + 8 * SIN_PER_C)  // 12032
#define SMEM_BYTES (SMEM_FLOATS * 4)          // 48128

// Duplicated packed weights: [b][c*9+kk][o][2]; each weight stored twice so a
// single LDS.64 yields the (w,w) pair an f32x2 FMA needs.
__device__ __align__(16) float g_wdup[64 * 72 * 8 * 2];

__global__ void gen_weights_kernel(const float* __restrict__ dw,
                                   const float* __restrict__ Wg,
                                   const float* __restrict__ bg) {
    int b = blockIdx.x;
    int t = threadIdx.x;          // 0..575
    int j = t >> 3;               // c*9 + kk  (input-channel*9 + tap)
    int o = t & 7;                // output channel (torch .view quirk)
    const float* dwp = dw + (b * 8 + o) * 8;
    const float* wgp = Wg + j * 8;
    float v = bg[j];
#pragma unroll
    for (int i = 0; i < 8; i++) v = fmaf(dwp[i], wgp[i], v);
    float* dst = g_wdup + ((b * 72 + j) * 8 + o) * 2;
    dst[0] = v;
    dst[1] = v;
}

__global__ __launch_bounds__(256, 3)
void conv_kernel(const float* __restrict__ x, float* __restrict__ out) {
    extern __shared__ float sm[];
    float* sw  = sm;               // 1152 floats duplicated weights
    float* sin = sm + SMEM_W;      // 8 ch x 10 rows x 136

    int bi = blockIdx.x;
    int b  = bi >> 6;              // batch
    int y0 = ((bi >> 1) & 31) * TY;
    int x0 = (bi & 1) * TX;
    int tx2 = threadIdx.x;         // col-pair index 0..63 -> cols 2*tx2, +1
    int g   = threadIdx.y;         // och-pair index 0..3 -> och 2g, 2g+1
    int tid = tx2 + (g << 6);      // 0..255

    // --- weights: 1152 floats = 288 float4 ---
    {
        const float4* wsrc = (const float4*)(g_wdup + b * 1152);
        if (tid < 144) {
            ((float4*)sw)[tid]       = wsrc[tid];
            ((float4*)sw)[tid + 144] = wsrc[tid + 144];
        }
    }

    // --- input tile: interior via LDG.128, scalar STS (odd base offset 3) ---
    const float* xb = x + (size_t)b * (8 * 65536);
    {
        int w5 = tid >> 5;         // 0..7
        int q  = tid & 31;         // quad 0..31
#pragma unroll
        for (int pass = 0; pass < 10; pass++) {
            int row = pass * 8 + w5;      // 0..79 = c*10 + t
            int c = row / 10;
            int t = row - c * 10;
            int gy = y0 - 1 + t;
            float4 v = make_float4(0.f, 0.f, 0.f, 0.f);
            if ((unsigned)gy < 256u)
                v = *(const float4*)(xb + c * 65536 + gy * 256 + x0 + 4 * q);
            float* d = sin + row * SIN_STRIDE + 4 * q + 3;
            d[0] = v.x; d[1] = v.y; d[2] = v.z; d[3] = v.w;
        }
        // halo: left (x0-1) -> pos 2, right (x0+128) -> pos 131
        if (tid < 160) {
            int side = tid >= 80;
            int r = side ? tid - 80 : tid;     // 0..79
            int c = r / 10;
            int t = r - c * 10;
            int gy = y0 - 1 + t;
            int gx = side ? (x0 + 128) : (x0 - 1);
            float v = 0.f;
            if (((unsigned)gy < 256u) && ((unsigned)gx < 256u))
                v = __ldg(xb + c * 65536 + gy * 256 + gx);
            sin[r * SIN_STRIDE + (side ? 131 : 2)] = v;
        }
    }
    __syncthreads();

    // --- accumulate: acc[r][oo] = f32x2 over (col 2tx2, col 2tx2+1) ---
    u64 acc[TY][2];
#pragma unroll
    for (int r = 0; r < TY; r++) { acc[r][0] = 0ull; acc[r][1] = 0ull; }

    const u64* swq = (const u64*)sw;

#pragma unroll 1
    for (int c = 0; c < 8; c++) {
        // 18 duplicated weight pairs: [kh][kw][oo]
        u64 w[3][3][2];
#pragma unroll
        for (int kk = 0; kk < 9; kk++) {
#pragma unroll
            for (int oo = 0; oo < 2; oo++)
                w[kk / 3][kk % 3][oo] = swq[(c * 9 + kk) * 8 + 2 * g + oo];
        }
        const float* sc = sin + c * SIN_PER_C + 2 * tx2;
#pragma unroll
        for (int t = 0; t < SIN_ROWS; t++) {
            const float* rowp = sc + t * SIN_STRIDE;
            u64 q0 = *(const u64*)(rowp + 2);   // cols (cx-1, cx)   : kw=0 pair
            u64 q1 = *(const u64*)(rowp + 4);   // cols (cx+1, cx+2) : kw=2 pair
            unsigned a0, a1, b0, b1;
            asm("mov.b64 {%0,%1}, %2;" : "=r"(a0), "=r"(a1) : "l"(q0));
            asm("mov.b64 {%0,%1}, %2;" : "=r"(b0), "=r"(b1) : "l"(q1));
            u64 pm;                              // cols (cx, cx+1)  : kw=1 pair
            asm("mov.b64 %0, {%1,%2};" : "=l"(pm) : "r"(a1), "r"(b0));
#pragma unroll
            for (int kh = 0; kh < 3; kh++) {
                int r = t - kh;                  // output row this tap feeds
                if (r >= 0 && r < TY) {
#pragma unroll
                    for (int oo = 0; oo < 2; oo++) {
                        asm("fma.rn.f32x2 %0, %1, %2, %0;"
                            : "+l"(acc[r][oo]) : "l"(q0), "l"(w[kh][0][oo]));
                        asm("fma.rn.f32x2 %0, %1, %2, %0;"
                            : "+l"(acc[r][oo]) : "l"(pm), "l"(w[kh][1][oo]));
                        asm("fma.rn.f32x2 %0, %1, %2, %0;"
                            : "+l"(acc[r][oo]) : "l"(q1), "l"(w[kh][2][oo]));
                    }
                }
            }
        }
    }

    // --- write out: (lo,hi) = cols (cx, cx+1), STG.64 per (row, och) ---
    float* ob = out + (size_t)b * (8 * 65536) + x0 + 2 * tx2;
#pragma unroll
    for (int r = 0; r < TY; r++) {
#pragma unroll
        for (int oo = 0; oo < 2; oo++) {
            int och = 2 * g + oo;
            *(u64*)(ob + och * 65536 + (y0 + r) * 256) = acc[r][oo];
        }
    }
}

extern "C" void kernel_launch(void* const* d_in, const int* in_sizes, int n_in,
                              void* d_out, int out_size) {
    const float* x  = (const float*)d_in[0];
    const float* dw = (const float*)d_in[1];
    const float* Wg = (const float*)d_in[2];
    const float* bg = (const float*)d_in[3];
    float* out = (float*)d_out;

    cudaFuncSetAttribute(conv_kernel, cudaFuncAttributeMaxDynamicSharedMemorySize,
                         SMEM_BYTES);

    gen_weights_kernel<<<64, 576>>>(dw, Wg, bg);

    dim3 blk(64, 4, 1);
    conv_kernel<<<64 * 32 * 2, blk, SMEM_BYTES>>>(x, out);
}